// round 1
// baseline (speedup 1.0000x reference)
#include <cuda_runtime.h>
#include <math.h>

#define TT 2048   // B*S tokens
#define SS 512
#define BB 4
#define HH 1024
#define NST 128   // SSM state dim
#define LL 6
#define VV 32000
#define NHD 8
#define FFD 4096
#define DHD 128

// ---------------- scratch (static device globals; no allocation) ----------------
__device__ float g_x [TT * HH];          // residual stream           8 MB
__device__ float g_t1[TT * FFD];         // temp A (holds qkv/ffn)   33.5 MB
__device__ float g_t2[TT * FFD];         // temp B                   33.5 MB
__device__ float g_sc[BB * NHD * SS * SS]; // attention scores       33.5 MB

// ---------------- embed: x = emb[ids] + pos ----------------
__global__ void embed_kernel(const int* __restrict__ ids, const float* __restrict__ emb,
                             const float* __restrict__ pos, float* __restrict__ x) {
    int t = blockIdx.x;
    int id = ids[t];
    int s = t % SS;
    const float* er = emb + (long long)id * HH;
    const float* pr = pos + (long long)s * HH;
    float* xr = x + (long long)t * HH;
    for (int j = threadIdx.x; j < HH; j += blockDim.x) xr[j] = er[j] + pr[j];
}

// ---------------- generic tiled GEMMs ----------------
#define BM 64
#define BN 64
#define BK 16
#define SPAD 4

// C[m,n] = act( alpha * sum_k A[m,k]*B[n,k] + bias[n] )   (NT: both row-major, K contiguous)
__global__ __launch_bounds__(256)
void gemm_nt(const float* __restrict__ A, const float* __restrict__ B,
             const float* __restrict__ bias, float* __restrict__ C,
             int M, int N, int K, int lda, int ldb, int ldc,
             long long sA, long long sB, long long sC,
             float alpha, int act) {
    A += sA * blockIdx.z; B += sB * blockIdx.z; C += sC * blockIdx.z;
    __shared__ __align__(16) float As[BK][BM + SPAD];
    __shared__ __align__(16) float Bs[BK][BN + SPAD];
    int tid = threadIdx.x;
    int tx = tid & 15, ty = tid >> 4;
    int row0 = blockIdx.y * BM, col0 = blockIdx.x * BN;
    float acc[4][4] = {};
    for (int k0 = 0; k0 < K; k0 += BK) {
#pragma unroll
        for (int j = 0; j < 4; j++) {
            int idx = tid + 256 * j;
            int r = idx >> 4, kk = idx & 15;
            As[kk][r] = A[(long long)(row0 + r) * lda + (k0 + kk)];
            Bs[kk][r] = B[(long long)(col0 + r) * ldb + (k0 + kk)];
        }
        __syncthreads();
#pragma unroll
        for (int kk = 0; kk < BK; kk++) {
            float4 a4 = *reinterpret_cast<const float4*>(&As[kk][ty * 4]);
            float4 b4 = *reinterpret_cast<const float4*>(&Bs[kk][tx * 4]);
            float af[4] = {a4.x, a4.y, a4.z, a4.w};
            float bf[4] = {b4.x, b4.y, b4.z, b4.w};
#pragma unroll
            for (int i = 0; i < 4; i++)
#pragma unroll
                for (int j = 0; j < 4; j++) acc[i][j] += af[i] * bf[j];
        }
        __syncthreads();
    }
#pragma unroll
    for (int i = 0; i < 4; i++) {
        long long m = row0 + ty * 4 + i;
#pragma unroll
        for (int j = 0; j < 4; j++) {
            int n = col0 + tx * 4 + j;
            float v = acc[i][j] * alpha + (bias ? bias[n] : 0.f);
            if (act == 1) v = 0.5f * v * (1.f + erff(v * 0.70710678118654752f)); // exact GELU
            C[m * ldc + n] = v;
        }
    }
}

// C[m,n] = sum_k A[m,k]*B[k,n]   (NN; B row-major [K,N] with row stride ldb)
__global__ __launch_bounds__(256)
void gemm_nn(const float* __restrict__ A, const float* __restrict__ B,
             const float* __restrict__ bias, float* __restrict__ C,
             int M, int N, int K, int lda, int ldb, int ldc,
             long long sA, long long sB, long long sC,
             float alpha, int act) {
    A += sA * blockIdx.z; B += sB * blockIdx.z; C += sC * blockIdx.z;
    __shared__ __align__(16) float As[BK][BM + SPAD];
    __shared__ __align__(16) float Bs[BK][BN + SPAD];
    int tid = threadIdx.x;
    int tx = tid & 15, ty = tid >> 4;
    int row0 = blockIdx.y * BM, col0 = blockIdx.x * BN;
    float acc[4][4] = {};
    for (int k0 = 0; k0 < K; k0 += BK) {
#pragma unroll
        for (int j = 0; j < 4; j++) {
            int idx = tid + 256 * j;
            int r = idx >> 4, kk = idx & 15;
            As[kk][r] = A[(long long)(row0 + r) * lda + (k0 + kk)];
            int n2 = idx & 63, kk2 = idx >> 6;
            Bs[kk2][n2] = B[(long long)(k0 + kk2) * ldb + (col0 + n2)];
        }
        __syncthreads();
#pragma unroll
        for (int kk = 0; kk < BK; kk++) {
            float4 a4 = *reinterpret_cast<const float4*>(&As[kk][ty * 4]);
            float4 b4 = *reinterpret_cast<const float4*>(&Bs[kk][tx * 4]);
            float af[4] = {a4.x, a4.y, a4.z, a4.w};
            float bf[4] = {b4.x, b4.y, b4.z, b4.w};
#pragma unroll
            for (int i = 0; i < 4; i++)
#pragma unroll
                for (int j = 0; j < 4; j++) acc[i][j] += af[i] * bf[j];
        }
        __syncthreads();
    }
#pragma unroll
    for (int i = 0; i < 4; i++) {
        long long m = row0 + ty * 4 + i;
#pragma unroll
        for (int j = 0; j < 4; j++) {
            int n = col0 + tx * 4 + j;
            float v = acc[i][j] * alpha + (bias ? bias[n] : 0.f);
            C[m * ldc + n] = v;
        }
    }
}

// ---------------- fused layernorm: out = scale*(LN(a + (coef[h]+off)*res) * g + b) ----------------
__global__ void ln_kernel(float* __restrict__ out, const float* __restrict__ a,
                          const float* __restrict__ res, const float* __restrict__ coef,
                          float coef_off, const float* __restrict__ g,
                          const float* __restrict__ bvec, float scale) {
    int t = blockIdx.x;
    __shared__ float red[256];
    float v[4];
    float s = 0.f;
#pragma unroll
    for (int j = 0; j < 4; j++) {
        int h = threadIdx.x + 256 * j;
        float xv = a[(long long)t * HH + h];
        if (res) {
            float c = (coef ? coef[h] : 0.f) + coef_off;
            xv += c * res[(long long)t * HH + h];
        }
        v[j] = xv;
        s += xv;
    }
    red[threadIdx.x] = s; __syncthreads();
    for (int o = 128; o > 0; o >>= 1) { if (threadIdx.x < o) red[threadIdx.x] += red[threadIdx.x + o]; __syncthreads(); }
    float mean = red[0] * (1.f / HH); __syncthreads();
    float s2 = 0.f;
#pragma unroll
    for (int j = 0; j < 4; j++) { float d = v[j] - mean; s2 += d * d; }
    red[threadIdx.x] = s2; __syncthreads();
    for (int o = 128; o > 0; o >>= 1) { if (threadIdx.x < o) red[threadIdx.x] += red[threadIdx.x + o]; __syncthreads(); }
    float rstd = rsqrtf(red[0] * (1.f / HH) + 1e-5f);
#pragma unroll
    for (int j = 0; j < 4; j++) {
        int h = threadIdx.x + 256 * j;
        out[(long long)t * HH + h] = ((v[j] - mean) * rstd * g[h] + bvec[h]) * scale;
    }
}

// ---------------- u = sigmoid(gl) * u ----------------
__global__ void gate_u_kernel(const float* __restrict__ gl, float* __restrict__ u, int n) {
    int i = blockIdx.x * blockDim.x + threadIdx.x;
    if (i < n) u[i] = u[i] / (1.f + expf(-gl[i]));
}

// ---------------- in-place sequential scan: s = A*s + u, per (b, n) ----------------
__global__ void scan_kernel(float* __restrict__ u, const float* __restrict__ A_log) {
    int b = blockIdx.x, n = threadIdx.x;     // 128 threads
    float a = expf(A_log[n]);
    float s = 0.f;
    long long base = (long long)b * SS * NST + n;
    for (int t0 = 0; t0 < SS; t0 += 8) {
        float uv[8];
#pragma unroll
        for (int j = 0; j < 8; j++) uv[j] = u[base + (long long)(t0 + j) * NST];
#pragma unroll
        for (int j = 0; j < 8; j++) { s = a * s + uv[j]; uv[j] = s; }
#pragma unroll
        for (int j = 0; j < 8; j++) u[base + (long long)(t0 + j) * NST] = uv[j];
    }
}

// ---------------- row softmax over 512 elements ----------------
__global__ void softmax512(float* __restrict__ p) {
    long long row = blockIdx.x;
    float* r = p + row * SS;
    int t = threadIdx.x;
    float v0 = r[t], v1 = r[t + 256];
    __shared__ float red[256];
    red[t] = fmaxf(v0, v1); __syncthreads();
    for (int o = 128; o > 0; o >>= 1) { if (t < o) red[t] = fmaxf(red[t], red[t + o]); __syncthreads(); }
    float m = red[0]; __syncthreads();
    float e0 = expf(v0 - m), e1 = expf(v1 - m);
    red[t] = e0 + e1; __syncthreads();
    for (int o = 128; o > 0; o >>= 1) { if (t < o) red[t] += red[t + o]; __syncthreads(); }
    float inv = 1.f / red[0];
    r[t] = e0 * inv; r[t + 256] = e1 * inv;
}

// ---------------- host orchestration ----------------
extern "C" void kernel_launch(void* const* d_in, const int* in_sizes, int n_in,
                              void* d_out, int out_size) {
    const int*   ids  = (const int*)  d_in[0];
    const float* emb  = (const float*)d_in[1];
    const float* pos  = (const float*)d_in[2];
    const float* A_log= (const float*)d_in[3];
    const float* WB   = (const float*)d_in[4];
    const float* WC   = (const float*)d_in[5];
    const float* Dp   = (const float*)d_in[6];
    const float* Wg   = (const float*)d_in[7];
    const float* bg   = (const float*)d_in[8];
    const float* Wout = (const float*)d_in[9];
    const float* bout = (const float*)d_in[10];
    const float* gs   = (const float*)d_in[11];
    const float* bs   = (const float*)d_in[12];
    const float* Wqkv = (const float*)d_in[13];
    const float* bqkv = (const float*)d_in[14];
    const float* Wo   = (const float*)d_in[15];
    const float* bo   = (const float*)d_in[16];
    const float* W1   = (const float*)d_in[17];
    const float* b1   = (const float*)d_in[18];
    const float* W2   = (const float*)d_in[19];
    const float* b2   = (const float*)d_in[20];
    const float* g1   = (const float*)d_in[21];
    const float* bn1  = (const float*)d_in[22];
    const float* g2   = (const float*)d_in[23];
    const float* bn2  = (const float*)d_in[24];
    const float* g3   = (const float*)d_in[25];
    const float* bn3  = (const float*)d_in[26];
    const float* gf   = (const float*)d_in[27];
    const float* bf   = (const float*)d_in[28];

    float *x, *t1, *t2, *sc;
    cudaGetSymbolAddress((void**)&x,  g_x);
    cudaGetSymbolAddress((void**)&t1, g_t1);
    cudaGetSymbolAddress((void**)&t2, g_t2);
    cudaGetSymbolAddress((void**)&sc, g_sc);

    embed_kernel<<<TT, 256>>>(ids, emb, pos, x);

    auto GEMM = [](const float* A, const float* B, const float* bias, float* C,
                   int M, int N, int K, int lda, int ldb, int ldc,
                   long long sA, long long sB, long long sC, int batch,
                   float alpha, int act) {
        dim3 grid(N / BN, M / BM, batch);
        gemm_nt<<<grid, 256>>>(A, B, bias, C, M, N, K, lda, ldb, ldc, sA, sB, sC, alpha, act);
    };

    for (int i = 0; i < LL; i++) {
        // ===== LinearStateLayer (SSM) =====
        GEMM(x, Wg + (long long)i * NST * HH, bg + (long long)i * NST, t1,
             TT, NST, HH, HH, HH, NST, 0, 0, 0, 1, 1.f, 0);               // gate logits
        GEMM(x, WB + (long long)i * NST * HH, nullptr, t2,
             TT, NST, HH, HH, HH, NST, 0, 0, 0, 1, 1.f, 0);               // B-projection
        gate_u_kernel<<<(TT * NST + 255) / 256, 256>>>(t1, t2, TT * NST); // u = sigm(g)*u
        scan_kernel<<<BB, NST>>>(t2, A_log + (long long)i * NST);         // in-place scan -> st
        GEMM(t2, WC + (long long)i * HH * NST, nullptr, t1,
             TT, HH, NST, NST, NST, HH, 0, 0, 0, 1, 1.f, 0);              // st @ WC^T
        // z = LN( stWC + (Dp+1)*x ; gs,bs )
        ln_kernel<<<TT, 256>>>(t2, t1, x, Dp + (long long)i * HH, 1.f,
                               gs + (long long)i * HH, bs + (long long)i * HH, 1.f);
        GEMM(t2, Wout + (long long)i * HH * HH, bout + (long long)i * HH, t1,
             TT, HH, HH, HH, HH, HH, 0, 0, 0, 1, 1.f, 0);                 // xs
        ln_kernel<<<TT, 256>>>(x, t1, x, nullptr, 1.f,
                               g1 + (long long)i * HH, bn1 + (long long)i * HH, 1.f);

        // ===== attention (odd layers) + memory fold (x2) =====
        if (i & 1) {
            GEMM(x, Wqkv + (long long)i * 3 * HH * HH, bqkv + (long long)i * 3 * HH, t1,
                 TT, 3 * HH, HH, HH, HH, 3 * HH, 0, 0, 0, 1, 1.f, 0);     // qkv
            float asc = 1.f / sqrtf((float)DHD);
            for (int b = 0; b < BB; b++) {
                const float* qb = t1 + (long long)b * SS * 3 * HH;
                const float* kb = qb + HH;
                GEMM(qb, kb, nullptr, sc + (long long)b * NHD * SS * SS,
                     SS, SS, DHD, 3 * HH, 3 * HH, SS,
                     DHD, DHD, (long long)SS * SS, NHD, asc, 0);          // scores
            }
            softmax512<<<BB * NHD * SS, 256>>>(sc);
            for (int b = 0; b < BB; b++) {
                const float* vb = t1 + (long long)b * SS * 3 * HH + 2 * HH;
                dim3 grid(DHD / BN, SS / BM, NHD);
                gemm_nn<<<grid, 256>>>(sc + (long long)b * NHD * SS * SS, vb, nullptr,
                                       t2 + (long long)b * SS * HH,
                                       SS, DHD, SS, SS, 3 * HH, HH,
                                       (long long)SS * SS, DHD, DHD, 1.f, 0); // att @ v
            }
            GEMM(t2, Wo + (long long)i * HH * HH, bo + (long long)i * HH, t1,
                 TT, HH, HH, HH, HH, HH, 0, 0, 0, 1, 1.f, 0);             // out proj
            ln_kernel<<<TT, 256>>>(x, t1, x, nullptr, 1.f,
                                   g2 + (long long)i * HH, bn2 + (long long)i * HH, 2.f);
        } else {
            ln_kernel<<<TT, 256>>>(x, x, nullptr, nullptr, 0.f,
                                   g2 + (long long)i * HH, bn2 + (long long)i * HH, 2.f);
        }

        // ===== FFN =====
        GEMM(x, W1 + (long long)i * FFD * HH, b1 + (long long)i * FFD, t1,
             TT, FFD, HH, HH, HH, FFD, 0, 0, 0, 1, 1.f, 1);               // gelu(x W1^T + b1)
        GEMM(t1, W2 + (long long)i * HH * FFD, b2 + (long long)i * HH, t2,
             TT, HH, FFD, FFD, FFD, HH, 0, 0, 0, 1, 1.f, 0);
        ln_kernel<<<TT, 256>>>(x, t2, x, nullptr, 1.f,
                               g3 + (long long)i * HH, bn3 + (long long)i * HH, 1.f);
    }

    // ===== final LN + tied lm_head =====
    ln_kernel<<<TT, 256>>>(t1, x, nullptr, nullptr, 0.f, gf, bf, 1.f);
    GEMM(t1, emb, nullptr, (float*)d_out, TT, VV, HH, HH, HH, VV, 0, 0, 0, 1, 1.f, 0);
}

// round 3
// speedup vs baseline: 2.3613x; 2.3613x over previous
#include <cuda_runtime.h>
#include <cuda_bf16.h>
#include <math.h>
#include <stdint.h>

#define TT 2048   // B*S tokens
#define SS 512
#define BB 4
#define HH 1024
#define NST 128
#define LL 6
#define VV 32000
#define NHD 8
#define FFD 4096
#define DHD 128

// ---------------- scratch ----------------
__device__ float g_x [TT * HH];
__device__ float g_t1[TT * FFD];
__device__ float g_t2[TT * FFD];
__device__ float g_sc[BB * NHD * SS * SS];
__device__ float g_vt[BB * NHD * DHD * SS];

// ---------------- embed ----------------
__global__ void embed_kernel(const int* __restrict__ ids, const float* __restrict__ emb,
                             const float* __restrict__ pos, float* __restrict__ x) {
    int t = blockIdx.x;
    int id = ids[t];
    int s = t % SS;
    const float* er = emb + (long long)id * HH;
    const float* pr = pos + (long long)s * HH;
    float* xr = x + (long long)t * HH;
    for (int j = threadIdx.x; j < HH; j += blockDim.x) xr[j] = er[j] + pr[j];
}

// ---------------- bf16x3 tensor-core NT GEMM ----------------
// C[m,n] = act(alpha * sum_k A[m,k]*B[n,k] + bias[n])
// Split each fp32 operand into bf16 hi + bf16 lo; accumulate hi*hi + lo*hi + hi*lo
// in fp32 via mma.sync.m16n8k16 -> ~17 mantissa bits effective.
// Block 128x128x32, 4 warps, warp tile 64x64 (4 mt x 8 nt of m16n8).
// Smem: rows of 16 bf162 words, word (r,j) at  r*16 + (j ^ (((r>>1)&3)<<2))
// -> conflict-free STS.64 staging and LDS.32 fragment gathers.
#define GBM 128
#define GBN 128
#define GBK 32

__device__ __forceinline__ uint32_t pack_hi(float x, float y) {
    __nv_bfloat162 h = __floats2bfloat162_rn(x, y);
    return *reinterpret_cast<uint32_t*>(&h);
}
__device__ __forceinline__ uint32_t pack_lo(float x, float y) {
    float hx = __bfloat162float(__float2bfloat16_rn(x));
    float hy = __bfloat162float(__float2bfloat16_rn(y));
    __nv_bfloat162 l = __floats2bfloat162_rn(x - hx, y - hy);
    return *reinterpret_cast<uint32_t*>(&l);
}

#define MMA_BF16(ACC, AFR, BF0, BF1)                                            \
    asm volatile(                                                               \
        "mma.sync.aligned.m16n8k16.row.col.f32.bf16.bf16.f32 "                  \
        "{%0,%1,%2,%3}, {%4,%5,%6,%7}, {%8,%9}, {%0,%1,%2,%3};"                 \
        : "+f"((ACC)[0]), "+f"((ACC)[1]), "+f"((ACC)[2]), "+f"((ACC)[3])        \
        : "r"((AFR)[0]), "r"((AFR)[1]), "r"((AFR)[2]), "r"((AFR)[3]),           \
          "r"(BF0), "r"(BF1))

__global__ __launch_bounds__(128, 2)
void gemm_bf16x3(const float* __restrict__ A, const float* __restrict__ B,
                 const float* __restrict__ bias, float* __restrict__ C,
                 int K, int lda, int ldb, int ldc, int zmod,
                 long long sAa, long long sAb, long long sBa, long long sBb,
                 long long sCa, long long sCb, float alpha, int act)
{
    int z = blockIdx.z;
    int zq = z / zmod, zr = z % zmod;
    A += (long long)zq * sAa + (long long)zr * sAb;
    B += (long long)zq * sBa + (long long)zr * sBb;
    C += (long long)zq * sCa + (long long)zr * sCb;

    // each tile: 128 rows x 16 bf162 words = 2048 words = 8KB
    __shared__ uint32_t AsH[2048], AsL[2048], BsH[2048], BsL[2048];

    int tid  = threadIdx.x;
    int lane = tid & 31, warp = tid >> 5;
    int wm = (warp & 1) * 64;
    int wn = (warp >> 1) * 64;
    int row0 = blockIdx.y * GBM, col0 = blockIdx.x * GBN;

    const float* Ag = A + (long long)row0 * lda;
    const float* Bg = B + (long long)col0 * ldb;

    float acc[4][8][4];
#pragma unroll
    for (int a = 0; a < 4; a++)
#pragma unroll
        for (int b = 0; b < 8; b++)
#pragma unroll
            for (int c = 0; c < 4; c++) acc[a][b][c] = 0.f;

    int g  = lane >> 2;    // 0..7
    int c0 = lane & 3;     // 0..3

    // precomputed fragment word addresses (ks=0; ks=1 adds 8 to j before swizzle,
    // swizzle only touches bits 2..3 so +8 commutes: addr(ks=1) = addr(ks=0) ^ 8)
    int aAddr[4][4], bAddr[8][2];
#pragma unroll
    for (int mt = 0; mt < 4; mt++)
#pragma unroll
        for (int i = 0; i < 4; i++) {
            int r = wm + mt * 16 + g + (i & 1) * 8;
            int j = c0 + (i >> 1) * 4;
            aAddr[mt][i] = r * 16 + (j ^ (((r >> 1) & 3) << 2));
        }
#pragma unroll
    for (int nt = 0; nt < 8; nt++)
#pragma unroll
        for (int i = 0; i < 2; i++) {
            int r = wn + nt * 8 + g;
            int j = c0 + i * 4;
            bAddr[nt][i] = r * 16 + (j ^ (((r >> 1) & 3) << 2));
        }

    for (int k0 = 0; k0 < K; k0 += GBK) {
        __syncthreads();
#pragma unroll
        for (int p = 0; p < 8; p++) {
            int f = tid + 128 * p;         // float4 id 0..1023
            int m = f >> 3, q = f & 7;     // row, k-quad
            int w0 = m * 16 + ((2 * q) ^ (((m >> 1) & 3) << 2));
            float4 a4 = *reinterpret_cast<const float4*>(Ag + (long long)m * lda + k0 + q * 4);
            float4 b4 = *reinterpret_cast<const float4*>(Bg + (long long)m * ldb + k0 + q * 4);
            *reinterpret_cast<uint2*>(AsH + w0) = make_uint2(pack_hi(a4.x, a4.y), pack_hi(a4.z, a4.w));
            *reinterpret_cast<uint2*>(AsL + w0) = make_uint2(pack_lo(a4.x, a4.y), pack_lo(a4.z, a4.w));
            *reinterpret_cast<uint2*>(BsH + w0) = make_uint2(pack_hi(b4.x, b4.y), pack_hi(b4.z, b4.w));
            *reinterpret_cast<uint2*>(BsL + w0) = make_uint2(pack_lo(b4.x, b4.y), pack_lo(b4.z, b4.w));
        }
        __syncthreads();
#pragma unroll
        for (int ks = 0; ks < 2; ks++) {
            int kx = ks * 8;
            uint32_t ah[4][4], al[4][4], bfr[8][2];
#pragma unroll
            for (int mt = 0; mt < 4; mt++)
#pragma unroll
                for (int i = 0; i < 4; i++) {
                    ah[mt][i] = AsH[aAddr[mt][i] ^ kx];
                    al[mt][i] = AsL[aAddr[mt][i] ^ kx];
                }
#pragma unroll
            for (int nt = 0; nt < 8; nt++)
#pragma unroll
                for (int i = 0; i < 2; i++) bfr[nt][i] = BsH[bAddr[nt][i] ^ kx];
            // hi*hi and lo*hi
#pragma unroll
            for (int mt = 0; mt < 4; mt++)
#pragma unroll
                for (int nt = 0; nt < 8; nt++) {
                    MMA_BF16(acc[mt][nt], ah[mt], bfr[nt][0], bfr[nt][1]);
                    MMA_BF16(acc[mt][nt], al[mt], bfr[nt][0], bfr[nt][1]);
                }
            // hi*lo
#pragma unroll
            for (int nt = 0; nt < 8; nt++)
#pragma unroll
                for (int i = 0; i < 2; i++) bfr[nt][i] = BsL[bAddr[nt][i] ^ kx];
#pragma unroll
            for (int mt = 0; mt < 4; mt++)
#pragma unroll
                for (int nt = 0; nt < 8; nt++)
                    MMA_BF16(acc[mt][nt], ah[mt], bfr[nt][0], bfr[nt][1]);
        }
    }

#pragma unroll
    for (int mt = 0; mt < 4; mt++) {
#pragma unroll
        for (int nt = 0; nt < 8; nt++) {
            int cb = col0 + wn + nt * 8 + 2 * c0;
            float bz0 = bias ? bias[cb] : 0.f;
            float bz1 = bias ? bias[cb + 1] : 0.f;
#pragma unroll
            for (int h = 0; h < 2; h++) {
                int r = row0 + wm + mt * 16 + g + h * 8;
                float v0 = acc[mt][nt][h * 2 + 0] * alpha + bz0;
                float v1 = acc[mt][nt][h * 2 + 1] * alpha + bz1;
                if (act) {
                    v0 = 0.5f * v0 * (1.f + erff(v0 * 0.70710678118654752f));
                    v1 = 0.5f * v1 * (1.f + erff(v1 * 0.70710678118654752f));
                }
                *reinterpret_cast<float2*>(&C[(long long)r * ldc + cb]) = make_float2(v0, v1);
            }
        }
    }
}

// ---------------- fused layernorm ----------------
__global__ void ln_kernel(float* __restrict__ out, const float* __restrict__ a,
                          const float* __restrict__ res, const float* __restrict__ coef,
                          float coef_off, const float* __restrict__ g,
                          const float* __restrict__ bvec, float scale) {
    int t = blockIdx.x;
    __shared__ float red[256];
    float v[4];
    float s = 0.f;
#pragma unroll
    for (int j = 0; j < 4; j++) {
        int h = threadIdx.x + 256 * j;
        float xv = a[(long long)t * HH + h];
        if (res) {
            float c = (coef ? coef[h] : 0.f) + coef_off;
            xv += c * res[(long long)t * HH + h];
        }
        v[j] = xv;
        s += xv;
    }
    red[threadIdx.x] = s; __syncthreads();
    for (int o = 128; o > 0; o >>= 1) { if (threadIdx.x < o) red[threadIdx.x] += red[threadIdx.x + o]; __syncthreads(); }
    float mean = red[0] * (1.f / HH); __syncthreads();
    float s2 = 0.f;
#pragma unroll
    for (int j = 0; j < 4; j++) { float d = v[j] - mean; s2 += d * d; }
    red[threadIdx.x] = s2; __syncthreads();
    for (int o = 128; o > 0; o >>= 1) { if (threadIdx.x < o) red[threadIdx.x] += red[threadIdx.x + o]; __syncthreads(); }
    float rstd = rsqrtf(red[0] * (1.f / HH) + 1e-5f);
#pragma unroll
    for (int j = 0; j < 4; j++) {
        int h = threadIdx.x + 256 * j;
        out[(long long)t * HH + h] = ((v[j] - mean) * rstd * g[h] + bvec[h]) * scale;
    }
}

// ---------------- u = sigmoid(gl) * u ----------------
__global__ void gate_u_kernel(const float* __restrict__ gl, float* __restrict__ u, int n) {
    int i = blockIdx.x * blockDim.x + threadIdx.x;
    if (i < n) u[i] = u[i] / (1.f + expf(-gl[i]));
}

// ---------------- sequential scan ----------------
__global__ void scan_kernel(float* __restrict__ u, const float* __restrict__ A_log) {
    int b = blockIdx.x, n = threadIdx.x;
    float a = expf(A_log[n]);
    float s = 0.f;
    long long base = (long long)b * SS * NST + n;
    for (int t0 = 0; t0 < SS; t0 += 8) {
        float uv[8];
#pragma unroll
        for (int j = 0; j < 8; j++) uv[j] = u[base + (long long)(t0 + j) * NST];
#pragma unroll
        for (int j = 0; j < 8; j++) { s = a * s + uv[j]; uv[j] = s; }
#pragma unroll
        for (int j = 0; j < 8; j++) u[base + (long long)(t0 + j) * NST] = uv[j];
    }
}

// ---------------- row softmax (512) ----------------
__global__ void softmax512(float* __restrict__ p) {
    long long row = blockIdx.x;
    float* r = p + row * SS;
    int t = threadIdx.x;
    float v0 = r[t], v1 = r[t + 256];
    __shared__ float red[256];
    red[t] = fmaxf(v0, v1); __syncthreads();
    for (int o = 128; o > 0; o >>= 1) { if (t < o) red[t] = fmaxf(red[t], red[t + o]); __syncthreads(); }
    float m = red[0]; __syncthreads();
    float e0 = expf(v0 - m), e1 = expf(v1 - m);
    red[t] = e0 + e1; __syncthreads();
    for (int o = 128; o > 0; o >>= 1) { if (t < o) red[t] += red[t + o]; __syncthreads(); }
    float inv = 1.f / red[0];
    r[t] = e0 * inv; r[t + 256] = e1 * inv;
}

// ---------------- V transpose: qkv[b][s][2H + h*128 + d] -> vt[bh][d][s] ----------------
__global__ void transpose_v(const float* __restrict__ qkv, float* __restrict__ vt) {
    __shared__ float tile[32][33];
    int b = blockIdx.z >> 3, h = blockIdx.z & 7;
    int s0 = blockIdx.x * 32, d0 = blockIdx.y * 32;
    int tx = threadIdx.x, ty = threadIdx.y;  // 32 x 8
    for (int i = ty; i < 32; i += 8)
        tile[i][tx] = qkv[((long long)(b * SS + s0 + i)) * (3 * HH) + 2 * HH + h * DHD + d0 + tx];
    __syncthreads();
    for (int i = ty; i < 32; i += 8)
        vt[((long long)blockIdx.z * DHD + d0 + i) * SS + s0 + tx] = tile[tx][i];
}

// ---------------- host orchestration ----------------
static inline void G(const float* A, const float* B, const float* bias, float* C,
                     int M, int N, int K, int lda, int ldb, int ldc,
                     int batch = 1, int zmod = 1,
                     long long sAa = 0, long long sAb = 0,
                     long long sBa = 0, long long sBb = 0,
                     long long sCa = 0, long long sCb = 0,
                     float alpha = 1.f, int act = 0) {
    dim3 grid(N / GBN, M / GBM, batch);
    gemm_bf16x3<<<grid, 128>>>(A, B, bias, C, K, lda, ldb, ldc, zmod,
                               sAa, sAb, sBa, sBb, sCa, sCb, alpha, act);
}

extern "C" void kernel_launch(void* const* d_in, const int* in_sizes, int n_in,
                              void* d_out, int out_size) {
    const int*   ids  = (const int*)  d_in[0];
    const float* emb  = (const float*)d_in[1];
    const float* pos  = (const float*)d_in[2];
    const float* A_log= (const float*)d_in[3];
    const float* WB   = (const float*)d_in[4];
    const float* WC   = (const float*)d_in[5];
    const float* Dp   = (const float*)d_in[6];
    const float* Wg   = (const float*)d_in[7];
    const float* bg   = (const float*)d_in[8];
    const float* Wout = (const float*)d_in[9];
    const float* bout = (const float*)d_in[10];
    const float* gs   = (const float*)d_in[11];
    const float* bs   = (const float*)d_in[12];
    const float* Wqkv = (const float*)d_in[13];
    const float* bqkv = (const float*)d_in[14];
    const float* Wo   = (const float*)d_in[15];
    const float* bo   = (const float*)d_in[16];
    const float* W1   = (const float*)d_in[17];
    const float* b1   = (const float*)d_in[18];
    const float* W2   = (const float*)d_in[19];
    const float* b2   = (const float*)d_in[20];
    const float* g1   = (const float*)d_in[21];
    const float* bn1  = (const float*)d_in[22];
    const float* g2   = (const float*)d_in[23];
    const float* bn2  = (const float*)d_in[24];
    const float* g3   = (const float*)d_in[25];
    const float* bn3  = (const float*)d_in[26];
    const float* gf   = (const float*)d_in[27];
    const float* bf   = (const float*)d_in[28];

    float *x, *t1, *t2, *sc, *vt;
    cudaGetSymbolAddress((void**)&x,  g_x);
    cudaGetSymbolAddress((void**)&t1, g_t1);
    cudaGetSymbolAddress((void**)&t2, g_t2);
    cudaGetSymbolAddress((void**)&sc, g_sc);
    cudaGetSymbolAddress((void**)&vt, g_vt);

    embed_kernel<<<TT, 256>>>(ids, emb, pos, x);

    for (int i = 0; i < LL; i++) {
        // ===== SSM =====
        G(x, Wg + (long long)i * NST * HH, bg + (long long)i * NST, t1,
          TT, NST, HH, HH, HH, NST);
        G(x, WB + (long long)i * NST * HH, nullptr, t2,
          TT, NST, HH, HH, HH, NST);
        gate_u_kernel<<<(TT * NST + 255) / 256, 256>>>(t1, t2, TT * NST);
        scan_kernel<<<BB, NST>>>(t2, A_log + (long long)i * NST);
        G(t2, WC + (long long)i * HH * NST, nullptr, t1,
          TT, HH, NST, NST, NST, HH);
        ln_kernel<<<TT, 256>>>(t2, t1, x, Dp + (long long)i * HH, 1.f,
                               gs + (long long)i * HH, bs + (long long)i * HH, 1.f);
        G(t2, Wout + (long long)i * HH * HH, bout + (long long)i * HH, t1,
          TT, HH, HH, HH, HH, HH);
        ln_kernel<<<TT, 256>>>(x, t1, x, nullptr, 1.f,
                               g1 + (long long)i * HH, bn1 + (long long)i * HH, 1.f);

        // ===== attention (odd layers) + memory fold (x2) =====
        if (i & 1) {
            G(x, Wqkv + (long long)i * 3 * HH * HH, bqkv + (long long)i * 3 * HH, t1,
              TT, 3 * HH, HH, HH, HH, 3 * HH);
            float asc = 1.f / sqrtf((float)DHD);
            G(t1, t1 + HH, nullptr, sc, SS, SS, DHD, 3 * HH, 3 * HH, SS,
              BB * NHD, NHD,
              (long long)SS * 3 * HH, DHD,
              (long long)SS * 3 * HH, DHD,
              (long long)NHD * SS * SS, (long long)SS * SS, asc, 0);
            softmax512<<<BB * NHD * SS, 256>>>(sc);
            {
                dim3 tg(SS / 32, DHD / 32, BB * NHD);
                transpose_v<<<tg, dim3(32, 8)>>>(t1, vt);
            }
            G(sc, vt, nullptr, t2, SS, DHD, SS, SS, SS, HH,
              BB * NHD, NHD,
              (long long)NHD * SS * SS, (long long)SS * SS,
              (long long)NHD * DHD * SS, (long long)DHD * SS,
              (long long)SS * HH, DHD, 1.f, 0);
            G(t2, Wo + (long long)i * HH * HH, bo + (long long)i * HH, t1,
              TT, HH, HH, HH, HH, HH);
            ln_kernel<<<TT, 256>>>(x, t1, x, nullptr, 1.f,
                                   g2 + (long long)i * HH, bn2 + (long long)i * HH, 2.f);
        } else {
            ln_kernel<<<TT, 256>>>(x, x, nullptr, nullptr, 0.f,
                                   g2 + (long long)i * HH, bn2 + (long long)i * HH, 2.f);
        }

        // ===== FFN =====
        G(x, W1 + (long long)i * FFD * HH, b1 + (long long)i * FFD, t1,
          TT, FFD, HH, HH, HH, FFD, 1, 1, 0, 0, 0, 0, 0, 0, 1.f, 1);
        G(t1, W2 + (long long)i * HH * FFD, b2 + (long long)i * HH, t2,
          TT, HH, FFD, FFD, FFD, HH);
        ln_kernel<<<TT, 256>>>(x, t2, x, nullptr, 1.f,
                               g3 + (long long)i * HH, bn3 + (long long)i * HH, 1.f);
    }

    // ===== final LN + tied lm_head =====
    ln_kernel<<<TT, 256>>>(t1, x, nullptr, nullptr, 0.f, gf, bf, 1.f);
    G(t1, emb, nullptr, (float*)d_out, TT, VV, HH, HH, HH, VV);
}